// round 2
// baseline (speedup 1.0000x reference)
#include <cuda_runtime.h>
#include <cuda_bf16.h>
#include <cstdint>

// Problem constants
#define BATCH 1024
#define NN    156
#define CIN   301
#define CH    128
#define EDGES 1564
#define ETOT  (EDGES + NN)      // edges + self loops = 1720
#define MTOT  (BATCH * NN)      // 159744 rows
// 1/sqrt(1 + 1e-5)
#define BN_INV_SQRT 0.9999950000374997f

// ---------------- scratch (static device memory; no cudaMalloc allowed) ----
__device__ float g_S0[(size_t)MTOT * CH];
__device__ float g_S1[(size_t)MTOT * CH];
__device__ int   g_row[ETOT];
__device__ int   g_col[ETOT];
__device__ float g_norm[ETOT];

// ---------------- packed fp32 helpers (sm_103a f32x2 pipe) -----------------
__device__ __forceinline__ unsigned long long pack2(float lo, float hi) {
    unsigned long long r;
    asm("mov.b64 %0, {%1, %2};" : "=l"(r) : "f"(lo), "f"(hi));
    return r;
}
__device__ __forceinline__ void ffma2(unsigned long long& d,
                                      unsigned long long a,
                                      unsigned long long b) {
    asm("fma.rn.f32x2 %0, %1, %2, %0;" : "+l"(d) : "l"(a), "l"(b));
}

// ---------------- kernel 1: graph preprocessing ----------------------------
// edge_index may be int64 OR int32 depending on how the harness materialized
// the jax array (jax x64 is disabled by default -> int32). Detect on device:
// for little-endian int64 values in [0,156), every odd 32-bit word is 0.
__global__ void build_kernel(const void* __restrict__ eiv) {
    const int* e32 = (const int*)eiv;
    __shared__ int is64;
    __shared__ float deg[NN];
    __shared__ float dinv[NN];
    int tid = threadIdx.x;

    if (tid == 0) {
        int all_zero = 1;
        for (int i = 1; i < 129; i += 2)
            if (e32[i] != 0) { all_zero = 0; break; }
        is64 = all_zero;
    }
    if (tid < NN) deg[tid] = 1.0f;                 // self-loop contribution
    __syncthreads();

    const int stride64 = is64;                     // 1 if int64, 0 if int32
    // index fetch: element i of logical int array (length 2*EDGES)
    auto fetch = [&](int i) -> int {
        return e32[i << stride64];
    };

    for (int e = tid; e < EDGES; e += blockDim.x) {
        int cl = fetch(EDGES + e);
        // clamp defensively (guarantees no OOB even if detection were wrong)
        cl = min(max(cl, 0), NN - 1);
        atomicAdd(&deg[cl], 1.0f);                 // deg over col
    }
    __syncthreads();
    if (tid < NN) dinv[tid] = rsqrtf(deg[tid]);
    __syncthreads();
    for (int e = tid; e < EDGES; e += blockDim.x) {
        int r  = min(max(fetch(e), 0), NN - 1);
        int cl = min(max(fetch(EDGES + e), 0), NN - 1);
        g_row[e]  = r;
        g_col[e]  = cl;
        g_norm[e] = dinv[r] * dinv[cl];
    }
    for (int n = tid; n < NN; n += blockDim.x) {
        g_row[EDGES + n]  = n;
        g_col[EDGES + n]  = n;
        g_norm[EDGES + n] = dinv[n] * dinv[n];
    }
}

// ---------------- kernel 2: tiled fp32 GEMM  out[M,128] = X[M,K] @ W[K,128] -
// BM=128, BN=128 (full width), BK=16, 256 threads, 8x8 microtile, f32x2 FMA.
#define BM 128
#define BK 16
#define APAD 4   // As row padded 128 -> 132 floats (keeps 16B align, kills STS conflicts)

__global__ void __launch_bounds__(256, 2) gemm_kernel(
    const float* __restrict__ X, const float* __restrict__ W,
    float* __restrict__ out, int K)
{
    __shared__ float As[BK][BM + APAD];
    __shared__ float Bs[BK][CH];

    const int tid = threadIdx.x;
    const size_t m0 = (size_t)blockIdx.x * BM;
    const int tm0 = (tid >> 4) * 8;      // 0..120
    const int tn0 = (tid & 15) * 8;      // 0..120

    unsigned long long acc[8][4];
#pragma unroll
    for (int i = 0; i < 8; i++)
#pragma unroll
        for (int j = 0; j < 4; j++) acc[i][j] = 0ULL;

    for (int k0 = 0; k0 < K; k0 += BK) {
        // load A tile (transposed into smem)
#pragma unroll
        for (int l = 0; l < 8; l++) {
            int idx = tid + l * 256;
            int kk  = idx & 15;
            int m   = idx >> 4;
            int kg  = k0 + kk;
            As[kk][m] = (kg < K) ? X[(m0 + m) * (size_t)K + kg] : 0.0f;
        }
        // load B tile: 16x128 floats via float4, coalesced
#pragma unroll
        for (int l = 0; l < 2; l++) {
            int idx = tid + l * 256;
            int kk  = idx >> 5;
            int j4  = idx & 31;
            int kg  = k0 + kk;
            float4 v = (kg < K) ? ((const float4*)W)[(size_t)kg * 32 + j4]
                                : make_float4(0.f, 0.f, 0.f, 0.f);
            *(float4*)&Bs[kk][j4 * 4] = v;
        }
        __syncthreads();

#pragma unroll
        for (int kk = 0; kk < BK; kk++) {
            float4 a0 = *(const float4*)&As[kk][tm0];
            float4 a1 = *(const float4*)&As[kk][tm0 + 4];
            const unsigned long long* bp =
                (const unsigned long long*)&Bs[kk][tn0];
            unsigned long long bv[4] = { bp[0], bp[1], bp[2], bp[3] };
            unsigned long long av[8];
            av[0] = pack2(a0.x, a0.x); av[1] = pack2(a0.y, a0.y);
            av[2] = pack2(a0.z, a0.z); av[3] = pack2(a0.w, a0.w);
            av[4] = pack2(a1.x, a1.x); av[5] = pack2(a1.y, a1.y);
            av[6] = pack2(a1.z, a1.z); av[7] = pack2(a1.w, a1.w);
#pragma unroll
            for (int i = 0; i < 8; i++)
#pragma unroll
                for (int j = 0; j < 4; j++)
                    ffma2(acc[i][j], av[i], bv[j]);
        }
        __syncthreads();
    }

    // epilogue: each acc ull holds 2 adjacent output columns
#pragma unroll
    for (int i = 0; i < 8; i++) {
        float* op = out + (m0 + tm0 + i) * (size_t)CH + tn0;
#pragma unroll
        for (int j = 0; j < 4; j++) {
            float2 v;
            v.x = __uint_as_float((unsigned)(acc[i][j] & 0xffffffffULL));
            v.y = __uint_as_float((unsigned)(acc[i][j] >> 32));
            *(float2*)(op + 2 * j) = v;
        }
    }
}

// ---------------- kernel 3: aggregation + bias + BN + ReLU ------------------
// One CTA per batch. smem accumulator [156][128] (79872 B, dynamic).
#define AGG_SMEM (NN * CH * 4)

__global__ void __launch_bounds__(1024, 2) agg_kernel(
    const float* __restrict__ T, float* __restrict__ out,
    const float* __restrict__ bias,
    const float* __restrict__ bnw, const float* __restrict__ bnb,
    int do_bnrelu)
{
    extern __shared__ float acc[];
    const int tid = threadIdx.x;
    const int b   = blockIdx.x;

    for (int i = tid; i < NN * CH; i += 1024) acc[i] = 0.0f;
    __syncthreads();

    const float* Tb = T + (size_t)b * NN * CH;
    const int c = tid & 127;       // channel
#pragma unroll 4
    for (int e = tid >> 7; e < ETOT; e += 8) {   // 8 edges in flight
        int   r  = g_row[e];
        int   cl = g_col[e];
        float nm = g_norm[e];
        float v  = Tb[r * CH + c] * nm;
        atomicAdd(&acc[cl * CH + c], v);
    }
    __syncthreads();

    float* ob = out + (size_t)b * NN * CH;
    for (int i = tid; i < NN * CH; i += 1024) {
        int cc  = i & 127;
        float v = acc[i] + bias[cc];
        if (do_bnrelu)
            v = fmaxf(fmaf(v, bnw[cc] * BN_INV_SQRT, bnb[cc]), 0.0f);
        ob[i] = v;
    }
}

// ---------------- launch ----------------------------------------------------
extern "C" void kernel_launch(void* const* d_in, const int* in_sizes, int n_in,
                              void* d_out, int out_size)
{
    const float* x    = (const float*)d_in[0];
    const void*  ei   = d_in[1];
    const float* W0   = (const float*)d_in[2];
    const float* b0   = (const float*)d_in[3];
    const float* bnw0 = (const float*)d_in[4];
    const float* bnb0 = (const float*)d_in[5];
    const float* W1   = (const float*)d_in[6];
    const float* b1   = (const float*)d_in[7];
    const float* bnw1 = (const float*)d_in[8];
    const float* bnb1 = (const float*)d_in[9];
    const float* W2   = (const float*)d_in[10];
    const float* b2   = (const float*)d_in[11];
    float*       out  = (float*)d_out;

    float *s0, *s1;
    cudaGetSymbolAddress((void**)&s0, g_S0);
    cudaGetSymbolAddress((void**)&s1, g_S1);
    cudaFuncSetAttribute(agg_kernel,
                         cudaFuncAttributeMaxDynamicSharedMemorySize, AGG_SMEM);

    const int gridM = MTOT / BM;   // 1248

    build_kernel<<<1, 256>>>(ei);

    // layer 0
    gemm_kernel<<<gridM, 256>>>(x, W0, s0, CIN);
    agg_kernel<<<BATCH, 1024, AGG_SMEM>>>(s0, s1, b0, bnw0, bnb0, 1);
    // layer 1
    gemm_kernel<<<gridM, 256>>>(s1, W1, s0, CH);
    agg_kernel<<<BATCH, 1024, AGG_SMEM>>>(s0, s1, b1, bnw1, bnb1, 1);
    // layer 2
    gemm_kernel<<<gridM, 256>>>(s1, W2, s0, CH);
    agg_kernel<<<BATCH, 1024, AGG_SMEM>>>(s0, out, b2, nullptr, nullptr, 0);
}

// round 3
// speedup vs baseline: 1.5465x; 1.5465x over previous
#include <cuda_runtime.h>
#include <cuda_bf16.h>
#include <cstdint>

// Problem constants
#define BATCH 1024
#define NN    156
#define CIN   301
#define CH    128
#define EDGES 1564
#define ETOT  (EDGES + NN)      // edges + self loops = 1720
#define MTOT  (BATCH * NN)      // 159744 rows
// 1/sqrt(1 + 1e-5)
#define BN_INV_SQRT 0.9999950000374997f

// ---------------- scratch (static device memory; no cudaMalloc allowed) ----
__device__ float g_S0[(size_t)MTOT * CH];
__device__ float g_S1[(size_t)MTOT * CH];
// CSC (sorted by destination) representation of normalized adjacency
__device__ int   g_ptr[NN + 1];
__device__ int   g_src[ETOT];
__device__ float g_nrm[ETOT];

// ---------------- packed fp32 helpers (sm_103a f32x2 pipe) -----------------
__device__ __forceinline__ unsigned long long pack2(float lo, float hi) {
    unsigned long long r;
    asm("mov.b64 %0, {%1, %2};" : "=l"(r) : "f"(lo), "f"(hi));
    return r;
}
__device__ __forceinline__ void ffma2(unsigned long long& d,
                                      unsigned long long a,
                                      unsigned long long b) {
    asm("fma.rn.f32x2 %0, %1, %2, %0;" : "+l"(d) : "l"(a), "l"(b));
}

// ---------------- kernel 1: graph preprocessing -> CSC ---------------------
// edge_index may be int64 OR int32 (jax x64 disabled -> int32). Detect:
// for little-endian int64 values in [0,156), every odd 32-bit word is 0.
__global__ void build_kernel(const void* __restrict__ eiv) {
    const int* e32 = (const int*)eiv;
    __shared__ int   is64;
    __shared__ float deg[NN];
    __shared__ float dinv[NN];
    __shared__ int   cnt[NN];
    __shared__ int   base[NN + 1];
    int tid = threadIdx.x;

    if (tid == 0) {
        int all_zero = 1;
        for (int i = 1; i < 129; i += 2)
            if (e32[i] != 0) { all_zero = 0; break; }
        is64 = all_zero;
    }
    if (tid < NN) { deg[tid] = 1.0f; cnt[tid] = 1; }  // self-loop
    __syncthreads();

    const int stride64 = is64;
    auto fetch = [&](int i) -> int {
        int v = e32[i << stride64];
        return min(max(v, 0), NN - 1);
    };

    for (int e = tid; e < EDGES; e += blockDim.x) {
        int cl = fetch(EDGES + e);
        atomicAdd(&deg[cl], 1.0f);
        atomicAdd(&cnt[cl], 1);
    }
    __syncthreads();
    if (tid < NN) dinv[tid] = rsqrtf(deg[tid]);
    // exclusive prefix sum over cnt (serial; 156 elems, negligible)
    if (tid == 0) {
        int run = 0;
        for (int n = 0; n < NN; n++) { base[n] = run; run += cnt[n]; }
        base[NN] = run;
    }
    __syncthreads();
    if (tid <= NN) g_ptr[tid] = base[tid];
    if (tid < NN) cnt[tid] = base[tid];   // reuse cnt as fill cursor
    __syncthreads();

    for (int e = tid; e < EDGES; e += blockDim.x) {
        int r  = fetch(e);
        int cl = fetch(EDGES + e);
        int pos = atomicAdd(&cnt[cl], 1);
        g_src[pos] = r;
        g_nrm[pos] = dinv[r] * dinv[cl];
    }
    __syncthreads();
    // self loops
    for (int n = tid; n < NN; n += blockDim.x) {
        int pos = atomicAdd(&cnt[n], 1);
        g_src[pos] = n;
        g_nrm[pos] = dinv[n] * dinv[n];
    }
}

// ---------------- kernel 2: tiled fp32 GEMM  out[M,128] = X[M,K] @ W[K,128] -
#define BM 128
#define BK 16
#define APAD 4

__global__ void __launch_bounds__(256, 2) gemm_kernel(
    const float* __restrict__ X, const float* __restrict__ W,
    float* __restrict__ out, int K)
{
    __shared__ float As[BK][BM + APAD];
    __shared__ float Bs[BK][CH];

    const int tid = threadIdx.x;
    const size_t m0 = (size_t)blockIdx.x * BM;
    const int tm0 = (tid >> 4) * 8;
    const int tn0 = (tid & 15) * 8;

    unsigned long long acc[8][4];
#pragma unroll
    for (int i = 0; i < 8; i++)
#pragma unroll
        for (int j = 0; j < 4; j++) acc[i][j] = 0ULL;

    for (int k0 = 0; k0 < K; k0 += BK) {
#pragma unroll
        for (int l = 0; l < 8; l++) {
            int idx = tid + l * 256;
            int kk  = idx & 15;
            int m   = idx >> 4;
            int kg  = k0 + kk;
            As[kk][m] = (kg < K) ? X[(m0 + m) * (size_t)K + kg] : 0.0f;
        }
#pragma unroll
        for (int l = 0; l < 2; l++) {
            int idx = tid + l * 256;
            int kk  = idx >> 5;
            int j4  = idx & 31;
            int kg  = k0 + kk;
            float4 v = (kg < K) ? ((const float4*)W)[(size_t)kg * 32 + j4]
                                : make_float4(0.f, 0.f, 0.f, 0.f);
            *(float4*)&Bs[kk][j4 * 4] = v;
        }
        __syncthreads();

#pragma unroll
        for (int kk = 0; kk < BK; kk++) {
            float4 a0 = *(const float4*)&As[kk][tm0];
            float4 a1 = *(const float4*)&As[kk][tm0 + 4];
            const unsigned long long* bp =
                (const unsigned long long*)&Bs[kk][tn0];
            unsigned long long bv[4] = { bp[0], bp[1], bp[2], bp[3] };
            unsigned long long av[8];
            av[0] = pack2(a0.x, a0.x); av[1] = pack2(a0.y, a0.y);
            av[2] = pack2(a0.z, a0.z); av[3] = pack2(a0.w, a0.w);
            av[4] = pack2(a1.x, a1.x); av[5] = pack2(a1.y, a1.y);
            av[6] = pack2(a1.z, a1.z); av[7] = pack2(a1.w, a1.w);
#pragma unroll
            for (int i = 0; i < 8; i++)
#pragma unroll
                for (int j = 0; j < 4; j++)
                    ffma2(acc[i][j], av[i], bv[j]);
        }
        __syncthreads();
    }

#pragma unroll
    for (int i = 0; i < 8; i++) {
        float* op = out + (m0 + tm0 + i) * (size_t)CH + tn0;
#pragma unroll
        for (int j = 0; j < 4; j++) {
            float2 v;
            v.x = __uint_as_float((unsigned)(acc[i][j] & 0xffffffffULL));
            v.y = __uint_as_float((unsigned)(acc[i][j] >> 32));
            *(float2*)(op + 2 * j) = v;
        }
    }
}

// ---------------- kernel 3: CSC-gather aggregation + bias + BN + ReLU -------
// No atomics: one thread per (dst row, channel), register accumulation.
// grid = (39 row-groups, 1024 batches), block = 512 (4 rows x 128 channels).
__global__ void __launch_bounds__(512) agg_kernel(
    const float* __restrict__ T, float* __restrict__ out,
    const float* __restrict__ bias,
    const float* __restrict__ bnw, const float* __restrict__ bnb,
    int do_bnrelu)
{
    const int tid = threadIdx.x;
    const int c   = tid & 127;
    const int n   = blockIdx.x * 4 + (tid >> 7);     // dst row (156 = 39*4)
    const int b   = blockIdx.y;

    const float* Tb = T + (size_t)b * NN * CH;
    const int beg = g_ptr[n];
    const int end = g_ptr[n + 1];

    float v0 = 0.0f, v1 = 0.0f;
    int e = beg;
    for (; e + 1 < end; e += 2) {
        int   s0 = g_src[e];     float m0 = g_nrm[e];
        int   s1 = g_src[e + 1]; float m1 = g_nrm[e + 1];
        v0 = fmaf(Tb[s0 * CH + c], m0, v0);
        v1 = fmaf(Tb[s1 * CH + c], m1, v1);
    }
    if (e < end) {
        int s = g_src[e];
        v0 = fmaf(Tb[s * CH + c], g_nrm[e], v0);
    }
    float v = v0 + v1 + bias[c];
    if (do_bnrelu)
        v = fmaxf(fmaf(v, bnw[c] * BN_INV_SQRT, bnb[c]), 0.0f);
    out[(size_t)b * NN * CH + n * CH + c] = v;
}

// ---------------- launch ----------------------------------------------------
extern "C" void kernel_launch(void* const* d_in, const int* in_sizes, int n_in,
                              void* d_out, int out_size)
{
    const float* x    = (const float*)d_in[0];
    const void*  ei   = d_in[1];
    const float* W0   = (const float*)d_in[2];
    const float* b0   = (const float*)d_in[3];
    const float* bnw0 = (const float*)d_in[4];
    const float* bnb0 = (const float*)d_in[5];
    const float* W1   = (const float*)d_in[6];
    const float* b1   = (const float*)d_in[7];
    const float* bnw1 = (const float*)d_in[8];
    const float* bnb1 = (const float*)d_in[9];
    const float* W2   = (const float*)d_in[10];
    const float* b2   = (const float*)d_in[11];
    float*       out  = (float*)d_out;

    float *s0, *s1;
    cudaGetSymbolAddress((void**)&s0, g_S0);
    cudaGetSymbolAddress((void**)&s1, g_S1);

    const int gridM = MTOT / BM;   // 1248
    dim3 agrid(NN / 4, BATCH);     // 39 x 1024

    build_kernel<<<1, 256>>>(ei);

    // layer 0
    gemm_kernel<<<gridM, 256>>>(x, W0, s0, CIN);
    agg_kernel<<<agrid, 512>>>(s0, s1, b0, bnw0, bnb0, 1);
    // layer 1
    gemm_kernel<<<gridM, 256>>>(s1, W1, s0, CH);
    agg_kernel<<<agrid, 512>>>(s0, s1, b1, bnw1, bnb1, 1);
    // layer 2
    gemm_kernel<<<gridM, 256>>>(s1, W2, s0, CH);
    agg_kernel<<<agrid, 512>>>(s0, out, b2, nullptr, nullptr, 0);
}

// round 4
// speedup vs baseline: 1.7121x; 1.1071x over previous
#include <cuda_runtime.h>
#include <cuda_bf16.h>
#include <cstdint>

// Problem constants
#define BATCH 1024
#define NN    156
#define CIN   301
#define CH    128
#define EDGES 1564
#define ETOT  (EDGES + NN)      // edges + self loops = 1720
#define MTOT  (BATCH * NN)      // 159744 rows
// 1/sqrt(1 + 1e-5)
#define BN_INV_SQRT 0.9999950000374997f

// ---------------- scratch (static device memory; no cudaMalloc allowed) ----
__device__ float g_S0[(size_t)MTOT * CH];
__device__ float g_S1[(size_t)MTOT * CH];
// CSC (sorted by destination) representation of normalized adjacency
__device__ int   g_ptr[NN + 1];
__device__ int   g_src[ETOT];
__device__ float g_nrm[ETOT];

// ---------------- packed fp32 helpers (sm_103a f32x2 pipe) -----------------
__device__ __forceinline__ unsigned long long pack2(float lo, float hi) {
    unsigned long long r;
    asm("mov.b64 %0, {%1, %2};" : "=l"(r) : "f"(lo), "f"(hi));
    return r;
}
__device__ __forceinline__ void ffma2(unsigned long long& d,
                                      unsigned long long a,
                                      unsigned long long b) {
    asm("fma.rn.f32x2 %0, %1, %2, %0;" : "+l"(d) : "l"(a), "l"(b));
}

// ---------------- kernel 1: graph preprocessing -> CSC ---------------------
// edge_index may be int64 OR int32 (jax x64 disabled -> int32). Detect:
// for little-endian int64 values in [0,156), every odd 32-bit word is 0.
__global__ void build_kernel(const void* __restrict__ eiv) {
    const int* e32 = (const int*)eiv;
    __shared__ int   is64;
    __shared__ float deg[NN];
    __shared__ float dinv[NN];
    __shared__ int   cnt[NN];
    __shared__ int   base[NN + 1];
    int tid = threadIdx.x;

    if (tid == 0) {
        int all_zero = 1;
        for (int i = 1; i < 129; i += 2)
            if (e32[i] != 0) { all_zero = 0; break; }
        is64 = all_zero;
    }
    if (tid < NN) { deg[tid] = 1.0f; cnt[tid] = 1; }  // self-loop
    __syncthreads();

    const int stride64 = is64;
    auto fetch = [&](int i) -> int {
        int v = e32[i << stride64];
        return min(max(v, 0), NN - 1);
    };

    for (int e = tid; e < EDGES; e += blockDim.x) {
        int cl = fetch(EDGES + e);
        atomicAdd(&deg[cl], 1.0f);
        atomicAdd(&cnt[cl], 1);
    }
    __syncthreads();
    if (tid < NN) dinv[tid] = rsqrtf(deg[tid]);
    if (tid == 0) {
        int run = 0;
        for (int n = 0; n < NN; n++) { base[n] = run; run += cnt[n]; }
        base[NN] = run;
    }
    __syncthreads();
    if (tid <= NN) g_ptr[tid] = base[tid];
    if (tid < NN) cnt[tid] = base[tid];   // reuse cnt as fill cursor
    __syncthreads();

    for (int e = tid; e < EDGES; e += blockDim.x) {
        int r  = fetch(e);
        int cl = fetch(EDGES + e);
        int pos = atomicAdd(&cnt[cl], 1);
        g_src[pos] = r;
        g_nrm[pos] = dinv[r] * dinv[cl];
    }
    __syncthreads();
    for (int n = tid; n < NN; n += blockDim.x) {
        int pos = atomicAdd(&cnt[n], 1);
        g_src[pos] = n;
        g_nrm[pos] = dinv[n] * dinv[n];
    }
}

// ---------------- kernel 2: tiled fp32 GEMM  out[M,128] = X[M,K] @ W[K,128] -
#define BM 128
#define BK 16
#define APAD 4

__global__ void __launch_bounds__(256, 2) gemm_kernel(
    const float* __restrict__ X, const float* __restrict__ W,
    float* __restrict__ out, int K)
{
    __shared__ float As[BK][BM + APAD];
    __shared__ float Bs[BK][CH];

    const int tid = threadIdx.x;
    const size_t m0 = (size_t)blockIdx.x * BM;
    const int tm0 = (tid >> 4) * 8;
    const int tn0 = (tid & 15) * 8;

    unsigned long long acc[8][4];
#pragma unroll
    for (int i = 0; i < 8; i++)
#pragma unroll
        for (int j = 0; j < 4; j++) acc[i][j] = 0ULL;

    for (int k0 = 0; k0 < K; k0 += BK) {
#pragma unroll
        for (int l = 0; l < 8; l++) {
            int idx = tid + l * 256;
            int kk  = idx & 15;
            int m   = idx >> 4;
            int kg  = k0 + kk;
            As[kk][m] = (kg < K) ? X[(m0 + m) * (size_t)K + kg] : 0.0f;
        }
#pragma unroll
        for (int l = 0; l < 2; l++) {
            int idx = tid + l * 256;
            int kk  = idx >> 5;
            int j4  = idx & 31;
            int kg  = k0 + kk;
            float4 v = (kg < K) ? ((const float4*)W)[(size_t)kg * 32 + j4]
                                : make_float4(0.f, 0.f, 0.f, 0.f);
            *(float4*)&Bs[kk][j4 * 4] = v;
        }
        __syncthreads();

#pragma unroll
        for (int kk = 0; kk < BK; kk++) {
            float4 a0 = *(const float4*)&As[kk][tm0];
            float4 a1 = *(const float4*)&As[kk][tm0 + 4];
            const unsigned long long* bp =
                (const unsigned long long*)&Bs[kk][tn0];
            unsigned long long bv[4] = { bp[0], bp[1], bp[2], bp[3] };
            unsigned long long av[8];
            av[0] = pack2(a0.x, a0.x); av[1] = pack2(a0.y, a0.y);
            av[2] = pack2(a0.z, a0.z); av[3] = pack2(a0.w, a0.w);
            av[4] = pack2(a1.x, a1.x); av[5] = pack2(a1.y, a1.y);
            av[6] = pack2(a1.z, a1.z); av[7] = pack2(a1.w, a1.w);
#pragma unroll
            for (int i = 0; i < 8; i++)
#pragma unroll
                for (int j = 0; j < 4; j++)
                    ffma2(acc[i][j], av[i], bv[j]);
        }
        __syncthreads();
    }

#pragma unroll
    for (int i = 0; i < 8; i++) {
        float* op = out + (m0 + tm0 + i) * (size_t)CH + tn0;
#pragma unroll
        for (int j = 0; j < 4; j++) {
            float2 v;
            v.x = __uint_as_float((unsigned)(acc[i][j] & 0xffffffffULL));
            v.y = __uint_as_float((unsigned)(acc[i][j] >> 32));
            *(float2*)(op + 2 * j) = v;
        }
    }
}

// ---------------- kernel 3: smem-staged CSC gather agg + bias + BN + ReLU ---
// One CTA per batch. Stage H_b[156x128] (80KB) + edge list (13.8KB) in smem,
// then gather from smem with register accumulation. Zero atomics, zero L2
// gather traffic.
#define AGG_SMEM (NN * CH * 4 + ETOT * 8)

__global__ void __launch_bounds__(512, 2) agg_kernel(
    const float* __restrict__ T, float* __restrict__ out,
    const float* __restrict__ bias,
    const float* __restrict__ bnw, const float* __restrict__ bnb,
    int do_bnrelu)
{
    extern __shared__ float sm[];
    float* Ts    = sm;                          // [NN*CH]
    int*   src_s = (int*)(sm + NN * CH);        // [ETOT]
    float* nrm_s = (float*)(src_s + ETOT);      // [ETOT]

    const int tid = threadIdx.x;
    const int b   = blockIdx.x;
    const float* Tb = T + (size_t)b * NN * CH;

    // stage activation tile (float4, coalesced): 4992 float4
    {
        const float4* Tb4 = (const float4*)Tb;
        float4* Ts4 = (float4*)Ts;
#pragma unroll
        for (int i = tid; i < NN * CH / 4; i += 512) Ts4[i] = Tb4[i];
    }
    // stage edge list
    for (int i = tid; i < ETOT; i += 512) {
        src_s[i] = g_src[i];
        nrm_s[i] = g_nrm[i];
    }
    __syncthreads();

    const int c = tid & 127;
    const float biasv = bias[c];
    const float bnwv  = do_bnrelu ? bnw[c] * BN_INV_SQRT : 0.0f;
    const float bnbv  = do_bnrelu ? bnb[c] : 0.0f;

    float* ob = out + (size_t)b * NN * CH;
    for (int n = tid >> 7; n < NN; n += 4) {
        const int beg = g_ptr[n];
        const int end = g_ptr[n + 1];
        float v0 = 0.0f, v1 = 0.0f;
        int e = beg;
        for (; e + 1 < end; e += 2) {
            v0 = fmaf(Ts[src_s[e]     * CH + c], nrm_s[e],     v0);
            v1 = fmaf(Ts[src_s[e + 1] * CH + c], nrm_s[e + 1], v1);
        }
        if (e < end)
            v0 = fmaf(Ts[src_s[e] * CH + c], nrm_s[e], v0);
        float v = v0 + v1 + biasv;
        if (do_bnrelu)
            v = fmaxf(fmaf(v, bnwv, bnbv), 0.0f);
        ob[n * CH + c] = v;
    }
}

// ---------------- launch ----------------------------------------------------
extern "C" void kernel_launch(void* const* d_in, const int* in_sizes, int n_in,
                              void* d_out, int out_size)
{
    const float* x    = (const float*)d_in[0];
    const void*  ei   = d_in[1];
    const float* W0   = (const float*)d_in[2];
    const float* b0   = (const float*)d_in[3];
    const float* bnw0 = (const float*)d_in[4];
    const float* bnb0 = (const float*)d_in[5];
    const float* W1   = (const float*)d_in[6];
    const float* b1   = (const float*)d_in[7];
    const float* bnw1 = (const float*)d_in[8];
    const float* bnb1 = (const float*)d_in[9];
    const float* W2   = (const float*)d_in[10];
    const float* b2   = (const float*)d_in[11];
    float*       out  = (float*)d_out;

    float *s0, *s1;
    cudaGetSymbolAddress((void**)&s0, g_S0);
    cudaGetSymbolAddress((void**)&s1, g_S1);
    cudaFuncSetAttribute(agg_kernel,
                         cudaFuncAttributeMaxDynamicSharedMemorySize, AGG_SMEM);

    const int gridM = MTOT / BM;   // 1248

    build_kernel<<<1, 256>>>(ei);

    // layer 0
    gemm_kernel<<<gridM, 256>>>(x, W0, s0, CIN);
    agg_kernel<<<BATCH, 512, AGG_SMEM>>>(s0, s1, b0, bnw0, bnb0, 1);
    // layer 1
    gemm_kernel<<<gridM, 256>>>(s1, W1, s0, CH);
    agg_kernel<<<BATCH, 512, AGG_SMEM>>>(s0, s1, b1, bnw1, bnb1, 1);
    // layer 2
    gemm_kernel<<<gridM, 256>>>(s1, W2, s0, CH);
    agg_kernel<<<BATCH, 512, AGG_SMEM>>>(s0, out, b2, nullptr, nullptr, 0);
}

// round 5
// speedup vs baseline: 2.0025x; 1.1696x over previous
#include <cuda_runtime.h>
#include <cuda_bf16.h>
#include <cstdint>

// Problem constants
#define BATCH 1024
#define NN    156
#define CIN   301
#define CH    128
#define EDGES 1564
#define ETOT  (EDGES + NN)      // edges + self loops = 1720
#define MTOT  (BATCH * NN)      // 159744 rows
// 1/sqrt(1 + 1e-5)
#define BN_INV_SQRT 0.9999950000374997f

// ---------------- scratch (static device memory; no cudaMalloc allowed) ----
__device__ float g_S0[(size_t)MTOT * CH];
__device__ float g_S1[(size_t)MTOT * CH];
// CSC (sorted by destination): ptr + packed (src, norm) per edge
__device__ int   g_ptr[NN + 1];
__device__ int2  g_edge[ETOT];

// ---------------- packed fp32 helpers (sm_103a f32x2 pipe) -----------------
__device__ __forceinline__ unsigned long long pack2(float lo, float hi) {
    unsigned long long r;
    asm("mov.b64 %0, {%1, %2};" : "=l"(r) : "f"(lo), "f"(hi));
    return r;
}
__device__ __forceinline__ void ffma2(unsigned long long& d,
                                      unsigned long long a,
                                      unsigned long long b) {
    asm("fma.rn.f32x2 %0, %1, %2, %0;" : "+l"(d) : "l"(a), "l"(b));
}

// ---------------- kernel 1: graph preprocessing -> packed CSC ---------------
// edge_index may be int64 OR int32 (jax x64 disabled -> int32). Detect:
// for little-endian int64 values in [0,156), every odd 32-bit word is 0.
__global__ void build_kernel(const void* __restrict__ eiv) {
    const int* e32 = (const int*)eiv;
    __shared__ int   is64;
    __shared__ float deg[NN];
    __shared__ float dinv[NN];
    __shared__ int   cnt[NN];
    __shared__ int   base[NN + 1];
    int tid = threadIdx.x;

    if (tid == 0) {
        int all_zero = 1;
        for (int i = 1; i < 129; i += 2)
            if (e32[i] != 0) { all_zero = 0; break; }
        is64 = all_zero;
    }
    if (tid < NN) { deg[tid] = 1.0f; cnt[tid] = 1; }  // self-loop
    __syncthreads();

    const int stride64 = is64;
    auto fetch = [&](int i) -> int {
        int v = e32[i << stride64];
        return min(max(v, 0), NN - 1);
    };

    for (int e = tid; e < EDGES; e += blockDim.x) {
        int cl = fetch(EDGES + e);
        atomicAdd(&deg[cl], 1.0f);
        atomicAdd(&cnt[cl], 1);
    }
    __syncthreads();
    if (tid < NN) dinv[tid] = rsqrtf(deg[tid]);
    if (tid == 0) {
        int run = 0;
        for (int n = 0; n < NN; n++) { base[n] = run; run += cnt[n]; }
        base[NN] = run;
    }
    __syncthreads();
    if (tid <= NN) g_ptr[tid] = base[tid];
    if (tid < NN) cnt[tid] = base[tid];   // reuse cnt as fill cursor
    __syncthreads();

    for (int e = tid; e < EDGES; e += blockDim.x) {
        int r  = fetch(e);
        int cl = fetch(EDGES + e);
        int pos = atomicAdd(&cnt[cl], 1);
        g_edge[pos] = make_int2(r, __float_as_int(dinv[r] * dinv[cl]));
    }
    __syncthreads();
    for (int n = tid; n < NN; n += blockDim.x) {
        int pos = atomicAdd(&cnt[n], 1);
        g_edge[pos] = make_int2(n, __float_as_int(dinv[n] * dinv[n]));
    }
}

// ---------------- kernel 2: tiled fp32 GEMM  out[M,128] = X[M,K] @ W[K,128] -
#define BM 128
#define BK 16
#define APAD 4

__global__ void __launch_bounds__(256, 2) gemm_kernel(
    const float* __restrict__ X, const float* __restrict__ W,
    float* __restrict__ out, int K)
{
    __shared__ float As[BK][BM + APAD];
    __shared__ float Bs[BK][CH];

    const int tid = threadIdx.x;
    const size_t m0 = (size_t)blockIdx.x * BM;
    const int tm0 = (tid >> 4) * 8;
    const int tn0 = (tid & 15) * 8;

    unsigned long long acc[8][4];
#pragma unroll
    for (int i = 0; i < 8; i++)
#pragma unroll
        for (int j = 0; j < 4; j++) acc[i][j] = 0ULL;

    for (int k0 = 0; k0 < K; k0 += BK) {
#pragma unroll
        for (int l = 0; l < 8; l++) {
            int idx = tid + l * 256;
            int kk  = idx & 15;
            int m   = idx >> 4;
            int kg  = k0 + kk;
            As[kk][m] = (kg < K) ? X[(m0 + m) * (size_t)K + kg] : 0.0f;
        }
#pragma unroll
        for (int l = 0; l < 2; l++) {
            int idx = tid + l * 256;
            int kk  = idx >> 5;
            int j4  = idx & 31;
            int kg  = k0 + kk;
            float4 v = (kg < K) ? ((const float4*)W)[(size_t)kg * 32 + j4]
                                : make_float4(0.f, 0.f, 0.f, 0.f);
            *(float4*)&Bs[kk][j4 * 4] = v;
        }
        __syncthreads();

#pragma unroll
        for (int kk = 0; kk < BK; kk++) {
            float4 a0 = *(const float4*)&As[kk][tm0];
            float4 a1 = *(const float4*)&As[kk][tm0 + 4];
            const unsigned long long* bp =
                (const unsigned long long*)&Bs[kk][tn0];
            unsigned long long bv[4] = { bp[0], bp[1], bp[2], bp[3] };
            unsigned long long av[8];
            av[0] = pack2(a0.x, a0.x); av[1] = pack2(a0.y, a0.y);
            av[2] = pack2(a0.z, a0.z); av[3] = pack2(a0.w, a0.w);
            av[4] = pack2(a1.x, a1.x); av[5] = pack2(a1.y, a1.y);
            av[6] = pack2(a1.z, a1.z); av[7] = pack2(a1.w, a1.w);
#pragma unroll
            for (int i = 0; i < 8; i++)
#pragma unroll
                for (int j = 0; j < 4; j++)
                    ffma2(acc[i][j], av[i], bv[j]);
        }
        __syncthreads();
    }

#pragma unroll
    for (int i = 0; i < 8; i++) {
        float* op = out + (m0 + tm0 + i) * (size_t)CH + tn0;
#pragma unroll
        for (int j = 0; j < 4; j++) {
            float2 v;
            v.x = __uint_as_float((unsigned)(acc[i][j] & 0xffffffffULL));
            v.y = __uint_as_float((unsigned)(acc[i][j] >> 32));
            *(float2*)(op + 2 * j) = v;
        }
    }
}

// ---------------- kernel 3: warp-per-row float4 gather agg ------------------
// One CTA per batch. Stage H_b[156x128] + packed edges in smem.
// Warp w handles dst rows w, w+16, ...; lane covers 4 channels (float4).
// Per edge: 1 broadcast LDS.64 + 1 LDS.128 gather + 4 FFMA.
#define AGG_SMEM (NN * CH * 4 + ETOT * 8 + (NN + 1) * 4)

__global__ void __launch_bounds__(512, 2) agg_kernel(
    const float* __restrict__ T, float* __restrict__ out,
    const float* __restrict__ bias,
    const float* __restrict__ bnw, const float* __restrict__ bnb,
    int do_bnrelu)
{
    extern __shared__ float sm[];
    float4* Ts4   = (float4*)sm;                     // [NN*32]
    int2*   edg_s = (int2*)(sm + NN * CH);           // [ETOT]
    int*    ptr_s = (int*)(edg_s + ETOT);            // [NN+1]

    const int tid  = threadIdx.x;
    const int warp = tid >> 5;
    const int lane = tid & 31;
    const int b    = blockIdx.x;

    // stage activation tile (float4, coalesced)
    {
        const float4* Tb4 = (const float4*)(T + (size_t)b * NN * CH);
#pragma unroll
        for (int i = tid; i < NN * 32; i += 512) Ts4[i] = Tb4[i];
    }
    for (int i = tid; i < ETOT; i += 512) edg_s[i] = g_edge[i];
    if (tid <= NN) ptr_s[tid] = g_ptr[tid];
    __syncthreads();

    // per-lane epilogue coefficients (4 channels each)
    float4 bias4 = ((const float4*)bias)[lane];
    float4 bnw4 = make_float4(0, 0, 0, 0), bnb4 = make_float4(0, 0, 0, 0);
    if (do_bnrelu) {
        bnw4 = ((const float4*)bnw)[lane];
        bnw4.x *= BN_INV_SQRT; bnw4.y *= BN_INV_SQRT;
        bnw4.z *= BN_INV_SQRT; bnw4.w *= BN_INV_SQRT;
        bnb4 = ((const float4*)bnb)[lane];
    }

    float4* ob4 = (float4*)(out + (size_t)b * NN * CH);
    for (int n = warp; n < NN; n += 16) {
        const int beg = ptr_s[n];
        const int end = ptr_s[n + 1];
        float4 a0 = make_float4(0, 0, 0, 0);
        float4 a1 = make_float4(0, 0, 0, 0);
        int e = beg;
        for (; e + 1 < end; e += 2) {
            int2 e0 = edg_s[e];
            int2 e1 = edg_s[e + 1];
            float4 t0 = Ts4[e0.x * 32 + lane];
            float4 t1 = Ts4[e1.x * 32 + lane];
            float m0 = __int_as_float(e0.y);
            float m1 = __int_as_float(e1.y);
            a0.x = fmaf(t0.x, m0, a0.x); a0.y = fmaf(t0.y, m0, a0.y);
            a0.z = fmaf(t0.z, m0, a0.z); a0.w = fmaf(t0.w, m0, a0.w);
            a1.x = fmaf(t1.x, m1, a1.x); a1.y = fmaf(t1.y, m1, a1.y);
            a1.z = fmaf(t1.z, m1, a1.z); a1.w = fmaf(t1.w, m1, a1.w);
        }
        if (e < end) {
            int2 e0 = edg_s[e];
            float4 t0 = Ts4[e0.x * 32 + lane];
            float m0 = __int_as_float(e0.y);
            a0.x = fmaf(t0.x, m0, a0.x); a0.y = fmaf(t0.y, m0, a0.y);
            a0.z = fmaf(t0.z, m0, a0.z); a0.w = fmaf(t0.w, m0, a0.w);
        }
        float4 v;
        v.x = a0.x + a1.x + bias4.x;
        v.y = a0.y + a1.y + bias4.y;
        v.z = a0.z + a1.z + bias4.z;
        v.w = a0.w + a1.w + bias4.w;
        if (do_bnrelu) {
            v.x = fmaxf(fmaf(v.x, bnw4.x, bnb4.x), 0.0f);
            v.y = fmaxf(fmaf(v.y, bnw4.y, bnb4.y), 0.0f);
            v.z = fmaxf(fmaf(v.z, bnw4.z, bnb4.z), 0.0f);
            v.w = fmaxf(fmaf(v.w, bnw4.w, bnb4.w), 0.0f);
        }
        ob4[n * 32 + lane] = v;
    }
}

// ---------------- launch ----------------------------------------------------
extern "C" void kernel_launch(void* const* d_in, const int* in_sizes, int n_in,
                              void* d_out, int out_size)
{
    const float* x    = (const float*)d_in[0];
    const void*  ei   = d_in[1];
    const float* W0   = (const float*)d_in[2];
    const float* b0   = (const float*)d_in[3];
    const float* bnw0 = (const float*)d_in[4];
    const float* bnb0 = (const float*)d_in[5];
    const float* W1   = (const float*)d_in[6];
    const float* b1   = (const float*)d_in[7];
    const float* bnw1 = (const float*)d_in[8];
    const float* bnb1 = (const float*)d_in[9];
    const float* W2   = (const float*)d_in[10];
    const float* b2   = (const float*)d_in[11];
    float*       out  = (float*)d_out;

    float *s0, *s1;
    cudaGetSymbolAddress((void**)&s0, g_S0);
    cudaGetSymbolAddress((void**)&s1, g_S1);
    cudaFuncSetAttribute(agg_kernel,
                         cudaFuncAttributeMaxDynamicSharedMemorySize, AGG_SMEM);

    const int gridM = MTOT / BM;   // 1248

    build_kernel<<<1, 256>>>(ei);

    // layer 0
    gemm_kernel<<<gridM, 256>>>(x, W0, s0, CIN);
    agg_kernel<<<BATCH, 512, AGG_SMEM>>>(s0, s1, b0, bnw0, bnb0, 1);
    // layer 1
    gemm_kernel<<<gridM, 256>>>(s1, W1, s0, CH);
    agg_kernel<<<BATCH, 512, AGG_SMEM>>>(s0, s1, b1, bnw1, bnb1, 1);
    // layer 2
    gemm_kernel<<<gridM, 256>>>(s1, W2, s0, CH);
    agg_kernel<<<BATCH, 512, AGG_SMEM>>>(s0, out, b2, nullptr, nullptr, 0);
}